// round 4
// baseline (speedup 1.0000x reference)
#include <cuda_runtime.h>
#include <math.h>

// ---------------- problem constants ----------------
#define N0   4096
#define EDG  131072
#define K1   3277      // ceil(0.8*4096)
#define K2   2622      // ceil(0.8*3277)
#define K3   2098      // ceil(0.8*2622)
#define KP1  3328      // K1 padded to 128
#define KP2  2688
#define KP3  2176
#define NP0  4096      // n padded to 16 (K dim of gemm)
#define NP1  3280
#define NP2  2624
#define CH   64
#define DSPLIT 32
#define RSPLIT 16

// ---------------- device scratch (no allocation allowed) ----------------
__device__ float g_A0[(size_t)N0*N0];
__device__ float g_A1[(size_t)K1*K1];
__device__ float g_A2[(size_t)K2*K2];
__device__ float g_A3[(size_t)K3*K3];
__device__ float g_R [(size_t)KP1*NP0];   // gathered rows  (k_pad x n_pad)
__device__ float g_Cg[(size_t)NP0*KP1];   // gathered cols  (n_pad x k_pad)
__device__ float g_x0[N0*CH];
__device__ float g_x1[K1*CH];
__device__ float g_x2[K2*CH];
__device__ float g_x3[K3*CH];
__device__ float g_xp[N0*CH];
__device__ float g_y [N0*CH];
__device__ float g_z [N0*CH];
__device__ float g_part [(size_t)RSPLIT*N0*CH];
__device__ float g_dpart[(size_t)DSPLIT*N0];
__device__ float g_dis[N0];
__device__ float g_slw[N0];
__device__ float g_score[N0];
__device__ float g_sval[N0];
__device__ int   g_perm0[K1];
__device__ int   g_perm1[K2];
__device__ int   g_perm2[K3];

static inline int cdiv(int a, int b) { return (a + b - 1) / b; }

// ---------------- elementwise ----------------
__global__ void k_zero(float* p, int n) {
    int i = blockIdx.x * blockDim.x + threadIdx.x;
    if (i < n) p[i] = 0.f;
}

__global__ void k_edges(const int* __restrict__ src, const int* __restrict__ dst,
                        float* __restrict__ A) {
    int i = blockIdx.x * blockDim.x + threadIdx.x;
    if (i >= EDG) return;
    int s = src[i], d = dst[i];
    if (s != d) atomicAdd(&A[(size_t)s * N0 + d], 1.0f);   // exact integer adds
}

__global__ void k_diag1(float* A) {
    int i = blockIdx.x * blockDim.x + threadIdx.x;
    if (i < N0) A[(size_t)i * N0 + i] += 1.0f;
}

// ---------------- degree / normalization ----------------
__global__ void k_colsum(const float* __restrict__ A, int n, float* __restrict__ dpart) {
    int c = blockIdx.x * blockDim.x + threadIdx.x;
    if (c >= n) return;
    int chunk = (n + DSPLIT - 1) / DSPLIT;
    int r0 = blockIdx.y * chunk;
    int r1 = min(n, r0 + chunk);
    float s = 0.f;
    for (int r = r0; r < r1; r++) s += A[(size_t)r * n + c];
    dpart[(size_t)blockIdx.y * n + c] = s;
}

__global__ void k_degfin(const float* __restrict__ A, int n,
                         const float* __restrict__ dpart,
                         float* __restrict__ dis, float* __restrict__ slw) {
    int c = blockIdx.x * blockDim.x + threadIdx.x;
    if (c >= n) return;
    float s = 0.f;
    for (int q = 0; q < DSPLIT; q++) s += dpart[(size_t)q * n + c];
    float dg = A[(size_t)c * n + c];
    float sl = (dg == 0.f) ? 2.f : 0.f;    // add_remaining_self_loops, fill=2
    float deg = s + sl;
    slw[c] = sl;
    dis[c] = (deg > 0.f) ? rsqrtf(deg) : 0.f;
}

// ---------------- x @ W, scaled by dis ----------------
template<int CIN, int COUT>
__global__ void k_xw(const float* __restrict__ x, int n, const float* __restrict__ W,
                     const float* __restrict__ dis,
                     float* __restrict__ y, float* __restrict__ z) {
    int idx = blockIdx.x * blockDim.x + threadIdx.x;
    if (idx >= n * COUT) return;
    int r = idx / COUT, j = idx % COUT;
    float s = 0.f;
    #pragma unroll
    for (int k = 0; k < CIN; k++) s += x[(size_t)r * CIN + k] * W[k * COUT + j];
    y[idx] = s;
    z[idx] = dis[r] * s;
}

// ---------------- out_part = (A^T z) split over rows ----------------
template<int COUT>
__global__ void k_atzp(const float* __restrict__ A, int n,
                       const float* __restrict__ z, float* __restrict__ part) {
    const int RC = 8;
    __shared__ float zs[RC][COUT];
    int c = blockIdx.x * blockDim.x + threadIdx.x;
    int chunk = (n + RSPLIT - 1) / RSPLIT;
    int r0b = blockIdx.y * chunk;
    int r1  = min(n, r0b + chunk);
    float acc[COUT];
    #pragma unroll
    for (int j = 0; j < COUT; j++) acc[j] = 0.f;
    for (int r0 = r0b; r0 < r1; r0 += RC) {
        __syncthreads();
        for (int t = threadIdx.x; t < RC * COUT; t += blockDim.x) {
            int rr = t / COUT, j = t % COUT;
            int r = r0 + rr;
            zs[rr][j] = (r < r1) ? z[(size_t)r * COUT + j] : 0.f;
        }
        __syncthreads();
        int rmax = min(RC, r1 - r0);
        if (c < n) {
            for (int rr = 0; rr < rmax; rr++) {
                float a = A[(size_t)(r0 + rr) * n + c];
                #pragma unroll
                for (int j = 0; j < COUT; j++) acc[j] += a * zs[rr][j];
            }
        }
    }
    if (c < n) {
        #pragma unroll
        for (int j = 0; j < COUT; j++)
            part[((size_t)blockIdx.y * n + c) * COUT + j] = acc[j];
    }
}

template<int COUT>
__global__ void k_fin(int n, const float* __restrict__ part,
                      const float* __restrict__ y, const float* __restrict__ dis,
                      const float* __restrict__ slw, const float* __restrict__ b,
                      int doRelu, float* __restrict__ out) {
    int idx = blockIdx.x * blockDim.x + threadIdx.x;
    if (idx >= n * COUT) return;
    int c = idx / COUT, j = idx % COUT;
    float s = 0.f;
    for (int q = 0; q < RSPLIT; q++) s += part[((size_t)q * n + c) * COUT + j];
    float dc = dis[c];
    float v = dc * (s + slw[c] * dc * y[idx]) + b[j];
    if (doRelu) v = fmaxf(v, 0.f);
    out[idx] = v;
}

// ---------------- top-k pooling ----------------
__global__ void k_score(const float* __restrict__ x, int n,
                        const float* __restrict__ p, float* __restrict__ s) {
    int r = blockIdx.x * blockDim.x + threadIdx.x;
    if (r >= n) return;
    float pp = 0.f, dot = 0.f;
    #pragma unroll
    for (int k = 0; k < CH; k++) {
        float pk = p[k];
        pp += pk * pk;
        dot += x[(size_t)r * CH + k] * pk;
    }
    s[r] = tanhf(dot / sqrtf(pp));
}

// rank = #{j : s[j] > s[i]  ||  (s[j]==s[i] && j<i)}  -> matches lax.top_k order
__global__ void k_rank(const float* __restrict__ score, int n, int k,
                       int* __restrict__ perm, float* __restrict__ sval) {
    __shared__ float ss[1024];
    int i = blockIdx.x * blockDim.x + threadIdx.x;
    float si = (i < n) ? score[i] : 0.f;
    int rank = 0;
    for (int j0 = 0; j0 < n; j0 += 1024) {
        int cnt = min(1024, n - j0);
        __syncthreads();
        for (int t = threadIdx.x; t < cnt; t += blockDim.x) ss[t] = score[j0 + t];
        __syncthreads();
        if (i < n) {
            for (int jj = 0; jj < cnt; jj++) {
                float sj = ss[jj];
                int j = j0 + jj;
                rank += (sj > si) || (sj == si && j < i);
            }
        }
    }
    if (i < n && rank < k) { perm[rank] = i; sval[rank] = si; }
}

__global__ void k_gpool(const float* __restrict__ x, const int* __restrict__ perm,
                        const float* __restrict__ sval, int k, float* __restrict__ xp) {
    int idx = blockIdx.x * blockDim.x + threadIdx.x;
    if (idx >= k * CH) return;
    int r = idx / CH, j = idx % CH;
    xp[idx] = x[(size_t)perm[r] * CH + j] * sval[r];
}

// A1[i,k] = (i==k) ? 1 : A[i,k]   (zero self-loops, add unit self-loops)
__global__ void k_gatherR(const float* __restrict__ A, int n, const int* __restrict__ perm,
                          int k, int kp, int np, float* __restrict__ R) {
    size_t idx = (size_t)blockIdx.x * blockDim.x + threadIdx.x;
    if (idx >= (size_t)kp * np) return;
    int r = (int)(idx / np), kk = (int)(idx % np);
    float v = 0.f;
    if (r < k && kk < n) {
        int pr = perm[r];
        v = (kk == pr) ? 1.0f : A[(size_t)pr * n + kk];
    }
    R[idx] = v;
}

__global__ void k_gatherC(const float* __restrict__ A, int n, const int* __restrict__ perm,
                          int k, int kp, int np, float* __restrict__ Cg) {
    size_t idx = (size_t)blockIdx.x * blockDim.x + threadIdx.x;
    if (idx >= (size_t)np * kp) return;
    int kk = (int)(idx / kp), c = (int)(idx % kp);
    float v = 0.f;
    if (kk < n && c < k) {
        int pc = perm[c];
        v = (kk == pc) ? 1.0f : A[(size_t)kk * n + pc];
    }
    Cg[idx] = v;
}

// ---------------- fp32 tiled SGEMM: C = A(MxK,lda) * B(KxN,ldb) ----------------
__global__ __launch_bounds__(256) void k_sgemm(int M, int N, int K,
        const float* __restrict__ A, int lda,
        const float* __restrict__ B, int ldb,
        float* __restrict__ C, int ldc, int zeroDiag) {
    __shared__ float As[16][128];
    __shared__ float Bs[16][128];
    const int tid = threadIdx.x;
    const int br = blockIdx.y * 128, bc = blockIdx.x * 128;
    const int arow = tid >> 2, akv = (tid & 3) << 2;
    const int bkr = tid >> 5, bcv = (tid & 31) << 2;
    const int tx = tid & 15, ty = tid >> 4;
    float acc[8][8];
    #pragma unroll
    for (int i = 0; i < 8; i++)
        #pragma unroll
        for (int j = 0; j < 8; j++) acc[i][j] = 0.f;

    for (int k0 = 0; k0 < K; k0 += 16) {
        float4 a0 = *(const float4*)&A[(size_t)(br + arow)      * lda + k0 + akv];
        float4 a1 = *(const float4*)&A[(size_t)(br + arow + 64) * lda + k0 + akv];
        float4 b0 = *(const float4*)&B[(size_t)(k0 + bkr)     * ldb + bc + bcv];
        float4 b1 = *(const float4*)&B[(size_t)(k0 + bkr + 8) * ldb + bc + bcv];
        __syncthreads();
        As[akv + 0][arow] = a0.x; As[akv + 1][arow] = a0.y;
        As[akv + 2][arow] = a0.z; As[akv + 3][arow] = a0.w;
        As[akv + 0][arow + 64] = a1.x; As[akv + 1][arow + 64] = a1.y;
        As[akv + 2][arow + 64] = a1.z; As[akv + 3][arow + 64] = a1.w;
        *(float4*)&Bs[bkr][bcv]     = b0;
        *(float4*)&Bs[bkr + 8][bcv] = b1;
        __syncthreads();
        #pragma unroll
        for (int kk = 0; kk < 16; kk++) {
            float af[8], bf[8];
            *(float4*)&af[0] = *(const float4*)&As[kk][ty * 8];
            *(float4*)&af[4] = *(const float4*)&As[kk][ty * 8 + 4];
            *(float4*)&bf[0] = *(const float4*)&Bs[kk][tx * 8];
            *(float4*)&bf[4] = *(const float4*)&Bs[kk][tx * 8 + 4];
            #pragma unroll
            for (int i = 0; i < 8; i++)
                #pragma unroll
                for (int j = 0; j < 8; j++) acc[i][j] += af[i] * bf[j];
        }
    }
    #pragma unroll
    for (int i = 0; i < 8; i++) {
        int r = br + ty * 8 + i;
        if (r < M) {
            #pragma unroll
            for (int j = 0; j < 8; j++) {
                int c = bc + tx * 8 + j;
                if (c < N) {
                    float v = acc[i][j];
                    if (zeroDiag && r == c) v = 0.f;
                    C[(size_t)r * ldc + c] = v;
                }
            }
        }
    }
}

// ---------------- unpool: res[perm[r]] += xup[r] ----------------
__global__ void k_unpool(float* __restrict__ res, const float* __restrict__ xup,
                         const int* __restrict__ perm, int k) {
    int idx = blockIdx.x * blockDim.x + threadIdx.x;
    if (idx >= k * CH) return;
    int r = idx / CH, j = idx % CH;
    res[(size_t)perm[r] * CH + j] += xup[idx];
}

// ---------------- host orchestration ----------------
struct DevPtrs {
    float *A0, *A1, *A2, *A3, *R, *Cg;
    float *x0, *x1, *x2, *x3, *xp, *y, *z, *part, *dpart, *dis, *slw, *score, *sval;
    int *perm0, *perm1, *perm2;
};
static DevPtrs P;
static bool g_init = false;

template<int CIN, int COUT>
static void gcn(const float* A, int n, const float* xin, const float* W,
                const float* b, bool relu, float* out) {
    dim3 cs(cdiv(n, 256), DSPLIT);
    k_colsum<<<cs, 256>>>(A, n, P.dpart);
    k_degfin<<<cdiv(n, 256), 256>>>(A, n, P.dpart, P.dis, P.slw);
    k_xw<CIN, COUT><<<cdiv(n * COUT, 256), 256>>>(xin, n, W, P.dis, P.y, P.z);
    dim3 ag(cdiv(n, 256), RSPLIT);
    k_atzp<COUT><<<ag, 256>>>(A, n, P.z, P.part);
    k_fin<COUT><<<cdiv(n * COUT, 256), 256>>>(n, P.part, P.y, P.dis, P.slw, b,
                                              relu ? 1 : 0, out);
}

static void pool_level(const float* A, int n, int k, int kp, int np,
                       const float* x, const float* p, int* perm, float* Anext) {
    k_score<<<cdiv(n, 256), 256>>>(x, n, p, P.score);
    k_rank<<<cdiv(n, 256), 256>>>(P.score, n, k, perm, P.sval);
    k_gpool<<<cdiv(k * CH, 256), 256>>>(x, perm, P.sval, k, P.xp);
    size_t tot = (size_t)kp * np;
    k_gatherR<<<(int)cdiv((int)tot, 256), 256>>>(A, n, perm, k, kp, np, P.R);
    k_gatherC<<<(int)cdiv((int)tot, 256), 256>>>(A, n, perm, k, kp, np, P.Cg);
    dim3 gg(kp / 128, kp / 128);
    k_sgemm<<<gg, 256>>>(k, k, np, P.R, np, P.Cg, kp, Anext, k, 1);
}

extern "C" void kernel_launch(void* const* d_in, const int* in_sizes, int n_in,
                              void* d_out, int out_size) {
    if (!g_init) {
        cudaGetSymbolAddress((void**)&P.A0, g_A0);
        cudaGetSymbolAddress((void**)&P.A1, g_A1);
        cudaGetSymbolAddress((void**)&P.A2, g_A2);
        cudaGetSymbolAddress((void**)&P.A3, g_A3);
        cudaGetSymbolAddress((void**)&P.R,  g_R);
        cudaGetSymbolAddress((void**)&P.Cg, g_Cg);
        cudaGetSymbolAddress((void**)&P.x0, g_x0);
        cudaGetSymbolAddress((void**)&P.x1, g_x1);
        cudaGetSymbolAddress((void**)&P.x2, g_x2);
        cudaGetSymbolAddress((void**)&P.x3, g_x3);
        cudaGetSymbolAddress((void**)&P.xp, g_xp);
        cudaGetSymbolAddress((void**)&P.y,  g_y);
        cudaGetSymbolAddress((void**)&P.z,  g_z);
        cudaGetSymbolAddress((void**)&P.part,  g_part);
        cudaGetSymbolAddress((void**)&P.dpart, g_dpart);
        cudaGetSymbolAddress((void**)&P.dis,   g_dis);
        cudaGetSymbolAddress((void**)&P.slw,   g_slw);
        cudaGetSymbolAddress((void**)&P.score, g_score);
        cudaGetSymbolAddress((void**)&P.sval,  g_sval);
        cudaGetSymbolAddress((void**)&P.perm0, g_perm0);
        cudaGetSymbolAddress((void**)&P.perm1, g_perm1);
        cudaGetSymbolAddress((void**)&P.perm2, g_perm2);
        g_init = true;
    }

    const float* x_in = (const float*)d_in[0];
    const int*   ei   = (const int*)d_in[1];
    const float* W0 = (const float*)d_in[2];  const float* b0 = (const float*)d_in[3];
    const float* W1 = (const float*)d_in[4];  const float* b1 = (const float*)d_in[5];
    const float* W2 = (const float*)d_in[6];  const float* b2 = (const float*)d_in[7];
    const float* W3 = (const float*)d_in[8];  const float* b3 = (const float*)d_in[9];
    const float* p1 = (const float*)d_in[10];
    const float* p2 = (const float*)d_in[11];
    const float* p3 = (const float*)d_in[12];
    const float* U0 = (const float*)d_in[13]; const float* c0 = (const float*)d_in[14];
    const float* U1 = (const float*)d_in[15]; const float* c1 = (const float*)d_in[16];
    const float* U2 = (const float*)d_in[17]; const float* c2 = (const float*)d_in[18];
    float* out = (float*)d_out;

    // A0 = dense adjacency with parallel-edge accumulation + unit self loops
    k_zero<<<cdiv(N0 * N0, 256), 256>>>(P.A0, N0 * N0);
    k_edges<<<cdiv(EDG, 256), 256>>>(ei, ei + EDG, P.A0);
    k_diag1<<<cdiv(N0, 256), 256>>>(P.A0);

    // ---- down path ----
    gcn<20, 64>(P.A0, N0, x_in, W0, b0, true, P.x0);

    pool_level(P.A0, N0, K1, KP1, NP0, P.x0, p1, P.perm0, P.A1);
    gcn<64, 64>(P.A1, K1, P.xp, W1, b1, true, P.x1);

    pool_level(P.A1, K1, K2, KP2, NP1, P.x1, p2, P.perm1, P.A2);
    gcn<64, 64>(P.A2, K2, P.xp, W2, b2, true, P.x2);

    pool_level(P.A2, K2, K3, KP3, NP2, P.x2, p3, P.perm2, P.A3);
    gcn<64, 64>(P.A3, K3, P.xp, W3, b3, true, P.x3);

    // ---- up path ----
    k_unpool<<<cdiv(K3 * CH, 256), 256>>>(P.x2, P.x3, P.perm2, K3);
    gcn<64, 64>(P.A2, K2, P.x2, U0, c0, true, P.xp);

    k_unpool<<<cdiv(K2 * CH, 256), 256>>>(P.x1, P.xp, P.perm1, K2);
    gcn<64, 64>(P.A1, K1, P.x1, U1, c1, true, P.xp);

    k_unpool<<<cdiv(K1 * CH, 256), 256>>>(P.x0, P.xp, P.perm0, K1);
    gcn<64, 20>(P.A0, N0, P.x0, U2, c2, false, out);
}

// round 7
// speedup vs baseline: 2.8003x; 2.8003x over previous
#include <cuda_runtime.h>
#include <cuda_fp16.h>
#include <math.h>
#include <stdint.h>

// ---------------- problem constants ----------------
#define N0   4096
#define EDG  131072
#define K1   3277      // ceil(0.8*4096)
#define K2   2622      // ceil(0.8*3277)
#define K3   2098      // ceil(0.8*2622)
#define KP1  3328      // K1 padded to 128 (GEMM M/N tiles)
#define KP2  2688
#define KP3  2176
#define KD1  4096      // GEMM K dim padded to 64
#define KD2  3328      // 3277 -> 3328
#define KD3  2624      // 2622 -> 2624
#define CH   64
#define DSPLIT 32
#define RSPLIT 16

// ---------------- device scratch (no allocation allowed) ----------------
__device__ float g_A0[(size_t)N0*N0];
__device__ float g_A1[(size_t)K1*K1];
__device__ float g_A2[(size_t)K2*K2];
__device__ float g_A3[(size_t)K3*K3];
__device__ __half g_Ah[(size_t)KP1*KD1];   // GEMM operand A, [M,K] row-major
__device__ __half g_Bh[(size_t)KP1*KD1];   // GEMM operand B, [N,K] row-major
__device__ float g_x0[N0*CH];
__device__ float g_x1[K1*CH];
__device__ float g_x2[K2*CH];
__device__ float g_x3[K3*CH];
__device__ float g_xp[N0*CH];
__device__ float g_y [N0*CH];
__device__ float g_z [N0*CH];
__device__ float g_part [(size_t)RSPLIT*N0*CH];
__device__ float g_dpart[(size_t)DSPLIT*N0];
__device__ float g_dis[N0];
__device__ float g_slw[N0];
__device__ float g_score[N0];
__device__ float g_sval[N0];
__device__ int   g_perm0[K1];
__device__ int   g_perm1[K2];
__device__ int   g_perm2[K3];

static inline int cdiv(int a, int b) { return (a + b - 1) / b; }

// ---------------- elementwise ----------------
__global__ void k_zero(float* p, int n) {
    int i = blockIdx.x * blockDim.x + threadIdx.x;
    if (i < n) p[i] = 0.f;
}

__global__ void k_edges(const int* __restrict__ src, const int* __restrict__ dst,
                        float* __restrict__ A) {
    int i = blockIdx.x * blockDim.x + threadIdx.x;
    if (i >= EDG) return;
    int s = src[i], d = dst[i];
    if (s != d) atomicAdd(&A[(size_t)s * N0 + d], 1.0f);   // exact integer adds
}

__global__ void k_diag1(float* A) {
    int i = blockIdx.x * blockDim.x + threadIdx.x;
    if (i < N0) A[(size_t)i * N0 + i] += 1.0f;
}

// ---------------- degree / normalization ----------------
__global__ void k_colsum(const float* __restrict__ A, int n, float* __restrict__ dpart) {
    int c = blockIdx.x * blockDim.x + threadIdx.x;
    if (c >= n) return;
    int chunk = (n + DSPLIT - 1) / DSPLIT;
    int r0 = blockIdx.y * chunk;
    int r1 = min(n, r0 + chunk);
    float s = 0.f;
    for (int r = r0; r < r1; r++) s += A[(size_t)r * n + c];
    dpart[(size_t)blockIdx.y * n + c] = s;
}

__global__ void k_degfin(const float* __restrict__ A, int n,
                         const float* __restrict__ dpart,
                         float* __restrict__ dis, float* __restrict__ slw) {
    int c = blockIdx.x * blockDim.x + threadIdx.x;
    if (c >= n) return;
    float s = 0.f;
    for (int q = 0; q < DSPLIT; q++) s += dpart[(size_t)q * n + c];
    float dg = A[(size_t)c * n + c];
    float sl = (dg == 0.f) ? 2.f : 0.f;    // add_remaining_self_loops, fill=2
    float deg = s + sl;
    slw[c] = sl;
    dis[c] = (deg > 0.f) ? rsqrtf(deg) : 0.f;
}

// ---------------- x @ W, scaled by dis ----------------
template<int CIN, int COUT>
__global__ void k_xw(const float* __restrict__ x, int n, const float* __restrict__ W,
                     const float* __restrict__ dis,
                     float* __restrict__ y, float* __restrict__ z) {
    int idx = blockIdx.x * blockDim.x + threadIdx.x;
    if (idx >= n * COUT) return;
    int r = idx / COUT, j = idx % COUT;
    float s = 0.f;
    #pragma unroll
    for (int k = 0; k < CIN; k++) s += x[(size_t)r * CIN + k] * W[k * COUT + j];
    y[idx] = s;
    z[idx] = dis[r] * s;
}

// ---------------- out_part = (A^T z) split over rows ----------------
template<int COUT>
__global__ void k_atzp(const float* __restrict__ A, int n,
                       const float* __restrict__ z, float* __restrict__ part) {
    const int RC = 8;
    __shared__ float zs[RC][COUT];
    int c = blockIdx.x * blockDim.x + threadIdx.x;
    int chunk = (n + RSPLIT - 1) / RSPLIT;
    int r0b = blockIdx.y * chunk;
    int r1  = min(n, r0b + chunk);
    float acc[COUT];
    #pragma unroll
    for (int j = 0; j < COUT; j++) acc[j] = 0.f;
    for (int r0 = r0b; r0 < r1; r0 += RC) {
        __syncthreads();
        for (int t = threadIdx.x; t < RC * COUT; t += blockDim.x) {
            int rr = t / COUT, j = t % COUT;
            int r = r0 + rr;
            zs[rr][j] = (r < r1) ? z[(size_t)r * COUT + j] : 0.f;
        }
        __syncthreads();
        int rmax = min(RC, r1 - r0);
        if (c < n) {
            for (int rr = 0; rr < rmax; rr++) {
                float a = A[(size_t)(r0 + rr) * n + c];
                #pragma unroll
                for (int j = 0; j < COUT; j++) acc[j] += a * zs[rr][j];
            }
        }
    }
    if (c < n) {
        #pragma unroll
        for (int j = 0; j < COUT; j++)
            part[((size_t)blockIdx.y * n + c) * COUT + j] = acc[j];
    }
}

template<int COUT>
__global__ void k_fin(int n, const float* __restrict__ part,
                      const float* __restrict__ y, const float* __restrict__ dis,
                      const float* __restrict__ slw, const float* __restrict__ b,
                      int doRelu, float* __restrict__ out) {
    int idx = blockIdx.x * blockDim.x + threadIdx.x;
    if (idx >= n * COUT) return;
    int c = idx / COUT, j = idx % COUT;
    float s = 0.f;
    for (int q = 0; q < RSPLIT; q++) s += part[((size_t)q * n + c) * COUT + j];
    float dc = dis[c];
    float v = dc * (s + slw[c] * dc * y[idx]) + b[j];
    if (doRelu) v = fmaxf(v, 0.f);
    out[idx] = v;
}

// ---------------- top-k pooling ----------------
__global__ void k_score(const float* __restrict__ x, int n,
                        const float* __restrict__ p, float* __restrict__ s) {
    int r = blockIdx.x * blockDim.x + threadIdx.x;
    if (r >= n) return;
    float pp = 0.f, dot = 0.f;
    #pragma unroll
    for (int k = 0; k < CH; k++) {
        float pk = p[k];
        pp += pk * pk;
        dot += x[(size_t)r * CH + k] * pk;
    }
    s[r] = tanhf(dot / sqrtf(pp));
}

// rank = #{j : s[j] > s[i]  ||  (s[j]==s[i] && j<i)}  -> matches lax.top_k order
__global__ void k_rank(const float* __restrict__ score, int n, int k,
                       int* __restrict__ perm, float* __restrict__ sval) {
    __shared__ float ss[1024];
    int i = blockIdx.x * blockDim.x + threadIdx.x;
    float si = (i < n) ? score[i] : 0.f;
    int rank = 0;
    for (int j0 = 0; j0 < n; j0 += 1024) {
        int cnt = min(1024, n - j0);
        __syncthreads();
        for (int t = threadIdx.x; t < cnt; t += blockDim.x) ss[t] = score[j0 + t];
        __syncthreads();
        if (i < n) {
            for (int jj = 0; jj < cnt; jj++) {
                float sj = ss[jj];
                int j = j0 + jj;
                rank += (sj > si) || (sj == si && j < i);
            }
        }
    }
    if (i < n && rank < k) { perm[rank] = i; sval[rank] = si; }
}

__global__ void k_gpool(const float* __restrict__ x, const int* __restrict__ perm,
                        const float* __restrict__ sval, int k, float* __restrict__ xp) {
    int idx = blockIdx.x * blockDim.x + threadIdx.x;
    if (idx >= k * CH) return;
    int r = idx / CH, j = idx % CH;
    xp[idx] = x[(size_t)perm[r] * CH + j] * sval[r];
}

// ---------------- gathers -> fp16 GEMM operands ----------------
// A operand [kp x kd]: Aop[r][kk] = A1[perm[r], kk]   (A1 = unit diag, A off-diag)
__global__ void k_gA(const float* __restrict__ A, int n, const int* __restrict__ perm,
                     int k, int kd, __half* __restrict__ H) {
    size_t idx = (size_t)blockIdx.x * blockDim.x + threadIdx.x;
    int r = (int)(idx / kd), kk = (int)(idx % kd);
    float v = 0.f;
    if (r < k && kk < n) {
        int pr = perm[r];
        v = (kk == pr) ? 1.0f : A[(size_t)pr * n + kk];
    }
    H[idx] = __float2half(v);   // small integers: exact
}

// B operand [kp x kd] ([N,K] layout): Bop[c][kk] = A1[kk, perm[c]]
__global__ void k_gB(const float* __restrict__ A, int n, const int* __restrict__ perm,
                     int k, int kd, __half* __restrict__ H) {
    size_t idx = (size_t)blockIdx.x * blockDim.x + threadIdx.x;
    int c = (int)(idx / kd), kk = (int)(idx % kd);
    float v = 0.f;
    if (c < k && kk < n) {
        int pc = perm[c];
        v = (kk == pc) ? 1.0f : A[(size_t)kk * n + pc];
    }
    H[idx] = __float2half(v);
}

// ---------------- mma.sync fp16 GEMM: C = A @ B^T ----------------
#define BM 128
#define BN 128
#define BK 64
#define STG 4
#define LDS_H 72                      // padded halves/row: 144B = 9 x 16B
#define STAGE_HALVES (2 * 128 * LDS_H)
#define SMEM_HGEMM (STG * STAGE_HALVES * 2)   // 147456 bytes

__device__ __forceinline__ uint32_t smem_u32(const void* p) {
    uint32_t a;
    asm("{ .reg .u64 t; cvta.to.shared.u64 t, %1; cvt.u32.u64 %0, t; }"
        : "=r"(a) : "l"(p));
    return a;
}
__device__ __forceinline__ void cpa16(uint32_t s, const void* g) {
    asm volatile("cp.async.cg.shared.global [%0], [%1], 16;" :: "r"(s), "l"(g));
}
#define CP_COMMIT() asm volatile("cp.async.commit_group;" ::: "memory")
#define CP_WAIT(n)  asm volatile("cp.async.wait_group %0;" :: "n"(n) : "memory")

__device__ __forceinline__ void ldm_x4(uint32_t* r, uint32_t addr) {
    asm volatile("ldmatrix.sync.aligned.m8n8.x4.shared.b16 {%0,%1,%2,%3}, [%4];"
        : "=r"(r[0]), "=r"(r[1]), "=r"(r[2]), "=r"(r[3]) : "r"(addr));
}
__device__ __forceinline__ void mma16816(float* d, const uint32_t* a,
                                         uint32_t b0, uint32_t b1) {
    asm volatile("mma.sync.aligned.m16n8k16.row.col.f32.f16.f16.f32 "
        "{%0,%1,%2,%3}, {%4,%5,%6,%7}, {%8,%9}, {%0,%1,%2,%3};"
        : "+f"(d[0]), "+f"(d[1]), "+f"(d[2]), "+f"(d[3])
        : "r"(a[0]), "r"(a[1]), "r"(a[2]), "r"(a[3]), "r"(b0), "r"(b1));
}

__global__ __launch_bounds__(256) void k_hgemm(
    int mreal, int nreal, int kd,
    const __half* __restrict__ Ap, const __half* __restrict__ Bp,
    float* __restrict__ C, int ldc, int zeroDiag)
{
    extern __shared__ __half sh[];
    const int tid = threadIdx.x;
    const int wid = tid >> 5, lane = tid & 31;
    const int bm = blockIdx.y * BM, bn = blockIdx.x * BN;
    const int wm0 = (wid & 3) * 32, wn0 = (wid >> 2) * 64;
    const int nch = kd / BK;

    const __half* Ag = Ap + (size_t)bm * kd;
    const __half* Bg = Bp + (size_t)bn * kd;

    const int lc8 = tid & 7;          // 16B column within 64-half chunk
    const int lr0 = tid >> 3;         // base row

    float acc[2][8][4];
    #pragma unroll
    for (int mt = 0; mt < 2; mt++)
        #pragma unroll
        for (int n8 = 0; n8 < 8; n8++)
            #pragma unroll
            for (int q = 0; q < 4; q++) acc[mt][n8][q] = 0.f;

    // prologue: stages 0..STG-2
    #pragma unroll
    for (int s = 0; s < STG - 1; s++) {
        __half* sA = sh + s * STAGE_HALVES;
        __half* sB = sA + 128 * LDS_H;
        const __half* Asrc = Ag + s * BK;
        const __half* Bsrc = Bg + s * BK;
        #pragma unroll
        for (int i = 0; i < 4; i++) {
            int row = lr0 + i * 32;
            cpa16(smem_u32(&sA[row * LDS_H + lc8 * 8]), Asrc + (size_t)row * kd + lc8 * 8);
            cpa16(smem_u32(&sB[row * LDS_H + lc8 * 8]), Bsrc + (size_t)row * kd + lc8 * 8);
        }
        CP_COMMIT();
    }

    for (int c = 0; c < nch; c++) {
        CP_WAIT(STG - 2);
        __syncthreads();

        // prefetch chunk c+STG-1
        {
            int cf = c + STG - 1;
            if (cf < nch) {
                int s = cf & (STG - 1);
                __half* sA = sh + s * STAGE_HALVES;
                __half* sB = sA + 128 * LDS_H;
                const __half* Asrc = Ag + cf * BK;
                const __half* Bsrc = Bg + cf * BK;
                #pragma unroll
                for (int i = 0; i < 4; i++) {
                    int row = lr0 + i * 32;
                    cpa16(smem_u32(&sA[row * LDS_H + lc8 * 8]),
                          Asrc + (size_t)row * kd + lc8 * 8);
                    cpa16(smem_u32(&sB[row * LDS_H + lc8 * 8]),
                          Bsrc + (size_t)row * kd + lc8 * 8);
                }
            }
            CP_COMMIT();
        }

        // compute on stage c % STG
        {
            int s = c & (STG - 1);
            const __half* sA = sh + s * STAGE_HALVES;
            const __half* sB = sA + 128 * LDS_H;
            // lane sub-addressing
            int ar = wm0 + (lane & 15);                 // A: + mt*16
            int ac = (lane >> 4) * 8;                   // A: + k16*16
            int br = wn0 + (lane & 7) + ((lane >> 4) & 1) * 8;   // B: + ng*16
            int bc = ((lane >> 3) & 1) * 8;             // B: + k16*16
            #pragma unroll
            for (int k16 = 0; k16 < 4; k16++) {
                uint32_t a[2][4];
                #pragma unroll
                for (int mt = 0; mt < 2; mt++)
                    ldm_x4(a[mt], smem_u32(&sA[(ar + mt * 16) * LDS_H + k16 * 16 + ac]));
                uint32_t b[4][4];
                #pragma unroll
                for (int ng = 0; ng < 4; ng++)
                    ldm_x4(b[ng], smem_u32(&sB[(br + ng * 16) * LDS_H + k16 * 16 + bc]));
                #pragma unroll
                for (int mt = 0; mt < 2; mt++)
                    #pragma unroll
                    for (int n8 = 0; n8 < 8; n8++) {
                        int ng = n8 >> 1, hi = (n8 & 1) << 1;
                        mma16816(acc[mt][n8], a[mt], b[ng][hi], b[ng][hi + 1]);
                    }
            }
        }
        __syncthreads();
    }

    // epilogue: direct coalesced stores (8x8 patches -> 8 full 32B sectors)
    int g = lane >> 2, tg = lane & 3;
    #pragma unroll
    for (int mt = 0; mt < 2; mt++) {
        #pragma unroll
        for (int n8 = 0; n8 < 8; n8++) {
            int r1 = bm + wm0 + mt * 16 + g;
            int r2 = r1 + 8;
            int c0 = bn + wn0 + n8 * 8 + tg * 2;
            float* a4 = acc[mt][n8];
            if (r1 < mreal) {
                if (c0 < nreal)
                    C[(size_t)r1 * ldc + c0] = (zeroDiag && r1 == c0) ? 0.f : a4[0];
                if (c0 + 1 < nreal)
                    C[(size_t)r1 * ldc + c0 + 1] = (zeroDiag && r1 == c0 + 1) ? 0.f : a4[1];
            }
            if (r2 < mreal) {
                if (c0 < nreal)
                    C[(size_t)r2 * ldc + c0] = (zeroDiag && r2 == c0) ? 0.f : a4[2];
                if (c0 + 1 < nreal)
                    C[(size_t)r2 * ldc + c0 + 1] = (zeroDiag && r2 == c0 + 1) ? 0.f : a4[3];
            }
        }
    }
}

// ---------------- unpool: res[perm[r]] += xup[r] ----------------
__global__ void k_unpool(float* __restrict__ res, const float* __restrict__ xup,
                         const int* __restrict__ perm, int k) {
    int idx = blockIdx.x * blockDim.x + threadIdx.x;
    if (idx >= k * CH) return;
    int r = idx / CH, j = idx % CH;
    res[(size_t)perm[r] * CH + j] += xup[idx];
}

// ---------------- host orchestration ----------------
struct DevPtrs {
    float *A0, *A1, *A2, *A3;
    __half *Ah, *Bh;
    float *x0, *x1, *x2, *x3, *xp, *y, *z, *part, *dpart, *dis, *slw, *score, *sval;
    int *perm0, *perm1, *perm2;
};
static DevPtrs P;
static bool g_init = false;

template<int CIN, int COUT>
static void gcn(const float* A, int n, const float* xin, const float* W,
                const float* b, bool relu, float* out) {
    dim3 cs(cdiv(n, 256), DSPLIT);
    k_colsum<<<cs, 256>>>(A, n, P.dpart);
    k_degfin<<<cdiv(n, 256), 256>>>(A, n, P.dpart, P.dis, P.slw);
    k_xw<CIN, COUT><<<cdiv(n * COUT, 256), 256>>>(xin, n, W, P.dis, P.y, P.z);
    dim3 ag(cdiv(n, 256), RSPLIT);
    k_atzp<COUT><<<ag, 256>>>(A, n, P.z, P.part);
    k_fin<COUT><<<cdiv(n * COUT, 256), 256>>>(n, P.part, P.y, P.dis, P.slw, b,
                                              relu ? 1 : 0, out);
}

static void pool_level(const float* A, int n, int k, int kp, int kd,
                       const float* x, const float* p, int* perm, float* Anext) {
    k_score<<<cdiv(n, 256), 256>>>(x, n, p, P.score);
    k_rank<<<cdiv(n, 256), 256>>>(P.score, n, k, perm, P.sval);
    k_gpool<<<cdiv(k * CH, 256), 256>>>(x, perm, P.sval, k, P.xp);
    size_t tot = (size_t)kp * kd;
    int nb = (int)((tot + 255) / 256);
    k_gA<<<nb, 256>>>(A, n, perm, k, kd, P.Ah);
    k_gB<<<nb, 256>>>(A, n, perm, k, kd, P.Bh);
    dim3 gg(kp / 128, kp / 128);
    k_hgemm<<<gg, 256, SMEM_HGEMM>>>(k, k, kd, P.Ah, P.Bh, Anext, k, 1);
}

extern "C" void kernel_launch(void* const* d_in, const int* in_sizes, int n_in,
                              void* d_out, int out_size) {
    if (!g_init) {
        cudaGetSymbolAddress((void**)&P.A0, g_A0);
        cudaGetSymbolAddress((void**)&P.A1, g_A1);
        cudaGetSymbolAddress((void**)&P.A2, g_A2);
        cudaGetSymbolAddress((void**)&P.A3, g_A3);
        cudaGetSymbolAddress((void**)&P.Ah, g_Ah);
        cudaGetSymbolAddress((void**)&P.Bh, g_Bh);
        cudaGetSymbolAddress((void**)&P.x0, g_x0);
        cudaGetSymbolAddress((void**)&P.x1, g_x1);
        cudaGetSymbolAddress((void**)&P.x2, g_x2);
        cudaGetSymbolAddress((void**)&P.x3, g_x3);
        cudaGetSymbolAddress((void**)&P.xp, g_xp);
        cudaGetSymbolAddress((void**)&P.y,  g_y);
        cudaGetSymbolAddress((void**)&P.z,  g_z);
        cudaGetSymbolAddress((void**)&P.part,  g_part);
        cudaGetSymbolAddress((void**)&P.dpart, g_dpart);
        cudaGetSymbolAddress((void**)&P.dis,   g_dis);
        cudaGetSymbolAddress((void**)&P.slw,   g_slw);
        cudaGetSymbolAddress((void**)&P.score, g_score);
        cudaGetSymbolAddress((void**)&P.sval,  g_sval);
        cudaGetSymbolAddress((void**)&P.perm0, g_perm0);
        cudaGetSymbolAddress((void**)&P.perm1, g_perm1);
        cudaGetSymbolAddress((void**)&P.perm2, g_perm2);
        cudaFuncSetAttribute(k_hgemm, cudaFuncAttributeMaxDynamicSharedMemorySize,
                             SMEM_HGEMM);
        g_init = true;
    }

    const float* x_in = (const float*)d_in[0];
    const int*   ei   = (const int*)d_in[1];
    const float* W0 = (const float*)d_in[2];  const float* b0 = (const float*)d_in[3];
    const float* W1 = (const float*)d_in[4];  const float* b1 = (const float*)d_in[5];
    const float* W2 = (const float*)d_in[6];  const float* b2 = (const float*)d_in[7];
    const float* W3 = (const float*)d_in[8];  const float* b3 = (const float*)d_in[9];
    const float* p1 = (const float*)d_in[10];
    const float* p2 = (const float*)d_in[11];
    const float* p3 = (const float*)d_in[12];
    const float* U0 = (const float*)d_in[13]; const float* c0 = (const float*)d_in[14];
    const float* U1 = (const float*)d_in[15]; const float* c1 = (const float*)d_in[16];
    const float* U2 = (const float*)d_in[17]; const float* c2 = (const float*)d_in[18];
    float* out = (float*)d_out;

    // A0 = dense adjacency with parallel-edge accumulation + unit self loops
    k_zero<<<cdiv(N0 * N0, 256), 256>>>(P.A0, N0 * N0);
    k_edges<<<cdiv(EDG, 256), 256>>>(ei, ei + EDG, P.A0);
    k_diag1<<<cdiv(N0, 256), 256>>>(P.A0);

    // ---- down path ----
    gcn<20, 64>(P.A0, N0, x_in, W0, b0, true, P.x0);

    pool_level(P.A0, N0, K1, KP1, KD1, P.x0, p1, P.perm0, P.A1);
    gcn<64, 64>(P.A1, K1, P.xp, W1, b1, true, P.x1);

    pool_level(P.A1, K1, K2, KP2, KD2, P.x1, p2, P.perm1, P.A2);
    gcn<64, 64>(P.A2, K2, P.xp, W2, b2, true, P.x2);

    pool_level(P.A2, K2, K3, KP3, KD3, P.x2, p3, P.perm2, P.A3);
    gcn<64, 64>(P.A3, K3, P.xp, W3, b3, true, P.x3);

    // ---- up path ----
    k_unpool<<<cdiv(K3 * CH, 256), 256>>>(P.x2, P.x3, P.perm2, K3);
    gcn<64, 64>(P.A2, K2, P.x2, U0, c0, true, P.xp);

    k_unpool<<<cdiv(K2 * CH, 256), 256>>>(P.x1, P.xp, P.perm1, K2);
    gcn<64, 64>(P.A1, K1, P.x1, U1, c1, true, P.xp);

    k_unpool<<<cdiv(K1 * CH, 256), 256>>>(P.x0, P.xp, P.perm0, K1);
    gcn<64, 20>(P.A0, N0, P.x0, U2, c2, false, out);
}